// round 15
// baseline (speedup 1.0000x reference)
#include <cuda_runtime.h>
#include <cuda_bf16.h>
#include <cstdint>

#define BATCH 4
#define L 4096
#define CM 192
#define DI 384
#define DS 16
#define DTR 12
#define M_ROWS (BATCH * L)   // 16384
#define NCH 128
#define CHL (L / NCH)        // 32
#define BDN (BATCH * DI * DS) // 24576
#define NX (2 * DI)          // 768
#define KC 576
#define NP 64
#define AP 36
#define ASTG (128 * AP)
#define HSTG (64 * AP)       // 64-row stage
#define QSTG (32 * AP)       // 32-row stage
#define BFRG 2048

// ---------------- scratch ----------------
__device__ float g_xi[(size_t)M_ROWS * DI];
__device__ float g_z[(size_t)M_ROWS * DI];
__device__ float g_u[(size_t)M_ROWS * DI];
__device__ float g_delta[(size_t)M_ROWS * DI];
__device__ float g_dtr[(size_t)M_ROWS * DTR];
__device__ float g_Bs[(size_t)M_ROWS * DS];
__device__ float g_Cs[(size_t)M_ROWS * DS];
__device__ float g_y[(size_t)M_ROWS * DI];
__device__ float g_hpart[(size_t)NCH * BDN];
__device__ float g_aP[(size_t)NCH * BDN];
__device__ float g_hin[(size_t)NCH * BDN];
__device__ float g_wtf[(size_t)NX * CM];
__device__ float g_pwhi[(size_t)NP * KC];
__device__ float g_pwlo[(size_t)NP * KC];
__device__ float g_wohi[(size_t)CM * DI];
__device__ float g_wolo[(size_t)CM * DI];

__device__ __forceinline__ uint32_t f2tf32(float f)
{
    uint32_t r;
    asm("cvt.rna.tf32.f32 %0, %1;" : "=r"(r) : "f"(f));
    return r;
}
__device__ __forceinline__ float tf32v(float f) { return __uint_as_float(f2tf32(f)); }

#define CP16(dst, src) \
    asm volatile("cp.async.cg.shared.global [%0], [%1], 16;" :: "r"(dst), "l"(src))
#define CP_COMMIT() asm volatile("cp.async.commit_group;" ::: "memory")
#define CP_WAIT0()  asm volatile("cp.async.wait_group 0;" ::: "memory")
#define CP_WAIT1()  asm volatile("cp.async.wait_group 1;" ::: "memory")

// ---------------- merged prep kernel ----------------
#define PREP_W  (CM * NX)
#define PREP_PW (NP * KC)
#define PREP_WO (CM * DI)
__global__ void k_prep_all(const float* __restrict__ Win, const float* __restrict__ Wx,
                           const float* __restrict__ Wp, const float* __restrict__ Wout)
{
    const int i = blockIdx.x * 256 + threadIdx.x;
    if (i < PREP_W) {
        const int k = i / NX, n = i % NX;
        const int ncb = n >> 6, j = (n & 63) >> 3, gg = n & 7;
        const int kci = k >> 5, ks = (k >> 3) & 3, cc = k & 7;
        const int slot = cc >> 2, tl = gg * 4 + (cc & 3);
        const size_t off = (size_t)ncb * 12288 + kci * 2048 + j * 256 + ks * 64 + tl * 2 + slot;
        g_wtf[off] = tf32v(Win[i]);
    } else if (i < PREP_W + PREP_PW) {
        const int e = i - PREP_W;
        const int n = e / KC, k = e % KC;
        float v = 0.f;
        if (n < 44) {
            if (k < DI) v = Wx[(size_t)k * 44 + n];
            else if (n >= 28) v = Wp[(size_t)(k - DI) * DS + (n - 28)];
        }
        const float hi = tf32v(v);
        g_pwhi[e] = hi;
        g_pwlo[e] = tf32v(v - hi);
    } else if (i < PREP_W + PREP_PW + PREP_WO) {
        const int e = i - PREP_W - PREP_PW;
        const int k = e / CM, n = e % CM;
        const float v = Wout[e];
        const float hi = tf32v(v);
        g_wohi[(size_t)n * DI + k] = hi;
        g_wolo[(size_t)n * DI + k] = tf32v(v - hi);
    }
}

__device__ __forceinline__ void mma_tf32(float* d, const uint32_t* a, const uint32_t* b)
{
    asm volatile(
        "mma.sync.aligned.m16n8k8.row.col.f32.tf32.tf32.f32 "
        "{%0,%1,%2,%3}, {%4,%5,%6,%7}, {%8,%9}, {%0,%1,%2,%3};"
        : "+f"(d[0]), "+f"(d[1]), "+f"(d[2]), "+f"(d[3])
        : "r"(a[0]), "r"(a[1]), "r"(a[2]), "r"(a[3]), "r"(b[0]), "r"(b[1]));
}

// ---------------- K1: xz = x @ W_in (tf32, 128x64 tile, frag-packed B) ----------------
__global__ __launch_bounds__(256) void k_gemm_tf32(const float* __restrict__ X)
{
    extern __shared__ float sm[];
    const uint32_t sbase = (uint32_t)__cvta_generic_to_shared(sm);
    const int tid = threadIdx.x;
    const int wid = tid >> 5, t = tid & 31;
    const int m0 = blockIdx.x * 128, ncb = blockIdx.y;
    const int wr = wid & 3, wc = wid >> 2;
    const int g = t >> 2, c = t & 3, c2 = c * 2;

    float acc[2][4][4];
#pragma unroll
    for (int mt = 0; mt < 2; mt++)
#pragma unroll
        for (int nt = 0; nt < 4; nt++)
#pragma unroll
            for (int e = 0; e < 4; e++) acc[mt][nt][e] = 0.f;

    const int lr = tid >> 1;
    const int lh = (tid & 1) * 16;
    const float* arow = X + (size_t)(m0 + lr) * CM + lh;
    const float* bbase = g_wtf + (size_t)ncb * 12288;
    const uint32_t adst = sbase + (uint32_t)(lr * AP + lh) * 4;
    const uint32_t bdst = sbase + (uint32_t)(9216 + tid * 4) * 4;

#define K1_ISSUE(i) do { \
        const int st_ = (i) & 1; const int kc_ = (i) * 32; \
        _Pragma("unroll") \
        for (int q = 0; q < 4; q++) \
            CP16(adst + (uint32_t)(st_ * ASTG + q * 4) * 4, arow + kc_ + q * 4); \
        CP16(bdst + (uint32_t)(st_ * BFRG) * 4, bbase + (i) * 2048 + tid * 4); \
        CP16(bdst + (uint32_t)(st_ * BFRG + 1024) * 4, bbase + (i) * 2048 + 1024 + tid * 4); \
        CP_COMMIT(); \
    } while (0)

    K1_ISSUE(0);

    for (int i = 0; i < 6; i++) {
        if (i + 1 < 6) { K1_ISSUE(i + 1); CP_WAIT1(); }
        else CP_WAIT0();
        __syncthreads();

        const float* cA = sm + (i & 1) * ASTG;
        const float* cB = sm + 9216 + (i & 1) * BFRG;
#pragma unroll
        for (int ks = 0; ks < 4; ks++) {
            const int K0 = ks * 8;
            uint32_t af[2][4];
#pragma unroll
            for (int mt = 0; mt < 2; mt++) {
                const int R = wr * 32 + mt * 16;
                af[mt][0] = f2tf32(cA[(R + g) * AP + K0 + c]);
                af[mt][1] = f2tf32(cA[(R + g + 8) * AP + K0 + c]);
                af[mt][2] = f2tf32(cA[(R + g) * AP + K0 + c + 4]);
                af[mt][3] = f2tf32(cA[(R + g + 8) * AP + K0 + c + 4]);
            }
#pragma unroll
            for (int nt = 0; nt < 4; nt++) {
                const int j = wc * 4 + nt;
                const float2 bv = *(const float2*)&cB[(j * 4 + ks) * 64 + t * 2];
                uint32_t bf[2] = {__float_as_uint(bv.x), __float_as_uint(bv.y)};
#pragma unroll
                for (int mt = 0; mt < 2; mt++)
                    mma_tf32(acc[mt][nt], af[mt], bf);
            }
        }
        __syncthreads();
    }
#undef K1_ISSUE

    const int n0 = ncb * 64;
    const bool toZ = (n0 >= DI);
#pragma unroll
    for (int mt = 0; mt < 2; mt++) {
#pragma unroll
        for (int nt = 0; nt < 4; nt++) {
            int nc = n0 + wc * 32 + nt * 8 + c2;
            if (toZ) nc -= DI;
            const int r0 = m0 + wr * 32 + mt * 16 + g;
            float* base = toZ ? g_z : g_xi;
            *(float2*)&base[(size_t)r0 * DI + nc] =
                make_float2(acc[mt][nt][0], acc[mt][nt][1]);
            *(float2*)&base[(size_t)(r0 + 8) * DI + nc] =
                make_float2(acc[mt][nt][2], acc[mt][nt][3]);
        }
    }
}

// ---------------- conv (R12 version) ----------------
__global__ __launch_bounds__(1024) void k_conv(const float* __restrict__ cw,
                                               const float* __restrict__ cb)
{
    extern __shared__ float cs[];
    const int b = blockIdx.z;
    const int d = blockIdx.y * 128 + threadIdx.x;
    const int h0 = (blockIdx.x >> 3) * 8;
    const int w0 = (blockIdx.x & 7) * 8;
    const int tx = threadIdx.x, ty = threadIdx.y;
    const size_t base = (size_t)b * L * DI;

#pragma unroll
    for (int i = 0; i < 13; i++) {
        const int p = ty + 8 * i;
        if (p < 100) {
            const int rr = p / 10, cc = p % 10;
            const int hh = h0 + rr - 1, ww = w0 + cc - 1;
            float v = 0.f;
            if (hh >= 0 && hh < 64 && ww >= 0 && ww < 64)
                v = g_xi[base + (size_t)(hh * 64 + ww) * DI + d];
            cs[p * 128 + tx] = v;
        }
    }
    __syncthreads();

    float W[9];
#pragma unroll
    for (int i = 0; i < 9; i++) W[i] = cw[d * 9 + i];
    const float bias = cb[d];

    float acc[8];
#pragma unroll
    for (int j = 0; j < 8; j++) acc[j] = bias;

#pragma unroll
    for (int r = 0; r < 3; r++) {
        float rv[10];
#pragma unroll
        for (int cc = 0; cc < 10; cc++) rv[cc] = cs[((ty + r) * 10 + cc) * 128 + tx];
#pragma unroll
        for (int j = 0; j < 8; j++) {
            acc[j] = fmaf(rv[j],     W[r * 3 + 0], acc[j]);
            acc[j] = fmaf(rv[j + 1], W[r * 3 + 1], acc[j]);
            acc[j] = fmaf(rv[j + 2], W[r * 3 + 2], acc[j]);
        }
    }
#pragma unroll
    for (int j = 0; j < 8; j++) {
        const float sig = 1.f / (1.f + __expf(-acc[j]));
        g_u[base + (size_t)((h0 + ty) * 64 + w0 + j) * DI + d] = acc[j] * sig;
    }
}

// ---------------- k_proj_mma: [u|prompt] @ Wcat, 32-row tiles (512 blocks) ----------------
// smem floats: A 2 stages @ 0 / 1152; Bh @ 2304 + st*2304; Bl @ 6912 + st*2304. 11520 fl.
__global__ __launch_bounds__(256) void k_proj_mma(const float* __restrict__ prompt)
{
    extern __shared__ float sm[];
    const uint32_t sbase = (uint32_t)__cvta_generic_to_shared(sm);
    const int tid = threadIdx.x;
    const int wid = tid >> 5, t = tid & 31;
    const int m0 = blockIdx.x * 32;
    const int wc = wid;                      // 8 col groups of 8
    const int g = t >> 2, c = t & 3, c2 = c * 2;

    float acc[2][4];
#pragma unroll
    for (int mt = 0; mt < 2; mt++)
#pragma unroll
        for (int e = 0; e < 4; e++) acc[mt][e] = 0.f;

    const int lr = tid >> 3;            // A row 0..31
    const int lh = (tid & 7) * 4;       // 4 floats
    const int lrB = tid >> 2;           // B row 0..63
    const int lhB = (tid & 3) * 8;
    const float* urow = g_u + (size_t)(m0 + lr) * DI + lh;
    const float* prow = prompt + (size_t)(m0 + lr) * CM + lh;
    const float* bhrow = g_pwhi + (size_t)lrB * KC + lhB;
    const float* blrow = g_pwlo + (size_t)lrB * KC + lhB;
    const uint32_t adst = sbase + (uint32_t)(lr * AP + lh) * 4;
    const uint32_t bhdst = sbase + (uint32_t)(2304 + lrB * AP + lhB) * 4;
    const uint32_t bldst = sbase + (uint32_t)(6912 + lrB * AP + lhB) * 4;

#define PJ_ISSUE(i) do { \
        const int st_ = (i) & 1; const int kc_ = (i) * 32; \
        const float* ar_ = (kc_ < DI) ? urow + kc_ : prow + (kc_ - DI); \
        CP16(adst + (uint32_t)(st_ * QSTG) * 4, ar_); \
        CP16(bhdst + (uint32_t)(st_ * HSTG) * 4, bhrow + kc_); \
        CP16(bhdst + (uint32_t)(st_ * HSTG + 4) * 4, bhrow + kc_ + 4); \
        CP16(bldst + (uint32_t)(st_ * HSTG) * 4, blrow + kc_); \
        CP16(bldst + (uint32_t)(st_ * HSTG + 4) * 4, blrow + kc_ + 4); \
        CP_COMMIT(); \
    } while (0)

    PJ_ISSUE(0);

    for (int i = 0; i < 18; i++) {
        if (i + 1 < 18) { PJ_ISSUE(i + 1); CP_WAIT1(); }
        else CP_WAIT0();
        __syncthreads();

        const float* cA = sm + (i & 1) * QSTG;
        const float* cBh = sm + 2304 + (i & 1) * HSTG;
        const float* cBl = sm + 6912 + (i & 1) * HSTG;
#pragma unroll
        for (int ks = 0; ks < 4; ks++) {
            const int K0 = ks * 8;
            uint32_t ah[2][4], al[2][4];
#pragma unroll
            for (int mt = 0; mt < 2; mt++) {
                const int R = mt * 16;
#pragma unroll
                for (int j = 0; j < 4; j++) {
                    const int rr = R + g + (j & 1) * 8;
                    const int ccol = K0 + c + (j >> 1) * 4;
                    const float raw = cA[rr * AP + ccol];
                    const float hv = tf32v(raw);
                    ah[mt][j] = __float_as_uint(hv);
                    al[mt][j] = f2tf32(raw - hv);
                }
            }
            const int N = wc * 8;
            uint32_t bh[2], bl[2];
            bh[0] = *(const uint32_t*)&cBh[(N + g) * AP + K0 + c];
            bh[1] = *(const uint32_t*)&cBh[(N + g) * AP + K0 + c + 4];
            bl[0] = *(const uint32_t*)&cBl[(N + g) * AP + K0 + c];
            bl[1] = *(const uint32_t*)&cBl[(N + g) * AP + K0 + c + 4];
#pragma unroll
            for (int mt = 0; mt < 2; mt++) {
                mma_tf32(acc[mt], ah[mt], bh);
                mma_tf32(acc[mt], ah[mt], bl);
                mma_tf32(acc[mt], al[mt], bh);
            }
        }
        __syncthreads();
    }
#undef PJ_ISSUE

    const int col = wc * 8 + c2;
#pragma unroll
    for (int mt = 0; mt < 2; mt++) {
        const int r0 = m0 + mt * 16 + g;
#pragma unroll
        for (int hrow = 0; hrow < 2; hrow++) {
            const size_t row = (size_t)(r0 + hrow * 8);
            const float v0 = acc[mt][hrow * 2 + 0];
            const float v1 = acc[mt][hrow * 2 + 1];
            if (col < DTR)
                *(float2*)&g_dtr[row * DTR + col] = make_float2(v0, v1);
            else if (col < DTR + DS)
                *(float2*)&g_Bs[row * DS + (col - DTR)] = make_float2(v0, v1);
            else if (col < 44)
                *(float2*)&g_Cs[row * DS + (col - DTR - DS)] = make_float2(v0, v1);
        }
    }
}

// ---------------- k_delta ----------------
__global__ void k_delta(const float* __restrict__ Wdt, const float* __restrict__ bdt)
{
    __shared__ float sd[8][DTR];
    const int tid = threadIdx.x;
    const int row0 = blockIdx.x * 8;
    if (tid < 8 * DTR) sd[tid / DTR][tid % DTR] = g_dtr[(size_t)(row0 + tid / DTR) * DTR + tid % DTR];
    __syncthreads();

    float w[DTR];
#pragma unroll
    for (int rr = 0; rr < DTR; rr++) w[rr] = Wdt[(size_t)rr * DI + tid];
    const float bb = bdt[tid];
#pragma unroll
    for (int rr = 0; rr < 8; rr++) {
        float acc = bb;
#pragma unroll
        for (int r2 = 0; r2 < DTR; r2++) acc = fmaf(sd[rr][r2], w[r2], acc);
        const float sp = acc > 20.f ? acc : log1pf(__expf(acc));
        g_delta[(size_t)(row0 + rr) * DI + tid] = sp;
    }
}

// ---------------- scan helpers ----------------
__device__ __forceinline__ void pow_chain(float e1, float* av)
{
    const float e2 = e1 * e1, e4 = e2 * e2, e8 = e4 * e4;
    av[0] = e1;       av[1] = e2;       av[2] = e2 * e1;   av[3] = e4;
    av[4] = e4 * e1;  av[5] = e4 * e2;  av[6] = e4 * av[2]; av[7] = e8;
    av[8] = e8 * e1;  av[9] = e8 * e2;  av[10] = e8 * av[2]; av[11] = e8 * e4;
    av[12] = e8 * av[4]; av[13] = e8 * av[5]; av[14] = e8 * av[6]; av[15] = e8 * e8;
}

__device__ __forceinline__ bool a_structured(const float* __restrict__ Alog, int d, float& A0)
{
    A0 = -__expf(Alog[(size_t)d * DS]);
    bool ok = true;
#pragma unroll
    for (int n = 1; n < DS; n++) {
        const float Av = -__expf(Alog[(size_t)d * DS + n]);
        ok &= fabsf(Av - (n + 1) * A0) <= 1e-4f * fabsf((n + 1) * A0);
    }
    return ok;
}

// ---------------- S1 ----------------
__global__ void k_scan1(const float* __restrict__ Alog)
{
    __shared__ float sB[CHL][DS];
    const int d = blockIdx.x * 128 + threadIdx.x;
    const int c = blockIdx.y;
    const int b = blockIdx.z;
    const int l0 = c * CHL;

    {
        const float4* src = (const float4*)g_Bs + ((size_t)b * L + l0) * 4;
        ((float4*)sB)[threadIdx.x] = src[threadIdx.x];
    }

    float A0;
    const bool st = a_structured(Alog, d, A0);
    __syncthreads();

    float h[DS];
#pragma unroll
    for (int n = 0; n < DS; n++) h[n] = 0.f;
    float dsum = 0.f;

    const float* dp = g_delta + ((size_t)b * L + l0) * DI + d;
    const float* up = g_u + ((size_t)b * L + l0) * DI + d;

    if (st) {
        for (int l = 0; l < CHL; l++) {
            const float dl = dp[(size_t)l * DI];
            const float du = dl * up[(size_t)l * DI];
            dsum += dl;
            float av[DS];
            pow_chain(__expf(dl * A0), av);
#pragma unroll
            for (int n = 0; n < DS; n++) h[n] = fmaf(av[n], h[n], du * sB[l][n]);
        }
        float av[DS];
        pow_chain(__expf(dsum * A0), av);
        const size_t base = (size_t)c * BDN + ((size_t)b * DI + d) * DS;
#pragma unroll
        for (int n = 0; n < DS; n++) {
            g_hpart[base + n] = h[n];
            g_aP[base + n] = av[n];
        }
    } else {
        float A[DS];
#pragma unroll
        for (int n = 0; n < DS; n++) A[n] = -__expf(Alog[(size_t)d * DS + n]);
        for (int l = 0; l < CHL; l++) {
            const float dl = dp[(size_t)l * DI];
            const float du = dl * up[(size_t)l * DI];
            dsum += dl;
#pragma unroll
            for (int n = 0; n < DS; n++)
                h[n] = fmaf(__expf(dl * A[n]), h[n], du * sB[l][n]);
        }
        const size_t base = (size_t)c * BDN + ((size_t)b * DI + d) * DS;
#pragma unroll
        for (int n = 0; n < DS; n++) {
            g_hpart[base + n] = h[n];
            g_aP[base + n] = __expf(A[n] * dsum);
        }
    }
}

// ---------------- S2 ----------------
__global__ void k_scan2()
{
    const int idx = blockIdx.x * 256 + threadIdx.x;
    if (idx >= BDN) return;
    float h = 0.f;
    for (int c = 0; c < NCH; c++) {
        const size_t o = (size_t)c * BDN + idx;
        g_hin[o] = h;
        h = fmaf(g_aP[o], h, g_hpart[o]);
    }
}

// ---------------- S3 ----------------
__global__ void k_scan3(const float* __restrict__ Alog, const float* __restrict__ Dvec)
{
    __shared__ float sB[CHL][DS];
    __shared__ float sC[CHL][DS];
    const int d = blockIdx.x * 128 + threadIdx.x;
    const int c = blockIdx.y;
    const int b = blockIdx.z;
    const int l0 = c * CHL;

    {
        const float4* srcB = (const float4*)g_Bs + ((size_t)b * L + l0) * 4;
        const float4* srcC = (const float4*)g_Cs + ((size_t)b * L + l0) * 4;
        ((float4*)sB)[threadIdx.x] = srcB[threadIdx.x];
        ((float4*)sC)[threadIdx.x] = srcC[threadIdx.x];
    }

    float A0;
    const bool st = a_structured(Alog, d, A0);
    const float Dd = Dvec[d];
    __syncthreads();

    float h[DS];
    {
        const size_t base = (size_t)c * BDN + ((size_t)b * DI + d) * DS;
#pragma unroll
        for (int n = 0; n < DS; n++) h[n] = g_hin[base + n];
    }

    const float* dp = g_delta + ((size_t)b * L + l0) * DI + d;
    const float* up = g_u + ((size_t)b * L + l0) * DI + d;
    float* yp = g_y + ((size_t)b * L + l0) * DI + d;

    if (st) {
        for (int l = 0; l < CHL; l++) {
            const float dl = dp[(size_t)l * DI];
            const float uu = up[(size_t)l * DI];
            const float du = dl * uu;
            float av[DS];
            pow_chain(__expf(dl * A0), av);
            float y = uu * Dd;
#pragma unroll
            for (int n = 0; n < DS; n++) {
                h[n] = fmaf(av[n], h[n], du * sB[l][n]);
                y = fmaf(h[n], sC[l][n], y);
            }
            yp[(size_t)l * DI] = y;
        }
    } else {
        float A[DS];
#pragma unroll
        for (int n = 0; n < DS; n++) A[n] = -__expf(Alog[(size_t)d * DS + n]);
        for (int l = 0; l < CHL; l++) {
            const float dl = dp[(size_t)l * DI];
            const float uu = up[(size_t)l * DI];
            const float du = dl * uu;
            float y = uu * Dd;
#pragma unroll
            for (int n = 0; n < DS; n++) {
                h[n] = fmaf(__expf(dl * A[n]), h[n], du * sB[l][n]);
                y = fmaf(h[n], sC[l][n], y);
            }
            yp[(size_t)l * DI] = y;
        }
    }
}

// ---------------- k_lngate ----------------
__global__ __launch_bounds__(256) void k_lngate(const float* __restrict__ lng,
                                                const float* __restrict__ lnb)
{
    const int tid = threadIdx.x;
    const int r0 = blockIdx.x * 16;
    const int warp = tid >> 5, lane = tid & 31;

#pragma unroll
    for (int rr = 0; rr < 2; rr++) {
        const int r = warp * 2 + rr;
        const size_t row = (size_t)(r0 + r);
        float v[12];
        float s = 0.f, sq = 0.f;
#pragma unroll
        for (int i = 0; i < 12; i++) {
            v[i] = g_y[row * DI + lane + 32 * i];
            s += v[i];
            sq = fmaf(v[i], v[i], sq);
        }
#pragma unroll
        for (int o = 16; o > 0; o >>= 1) {
            s += __shfl_xor_sync(0xFFFFFFFFu, s, o);
            sq += __shfl_xor_sync(0xFFFFFFFFu, sq, o);
        }
        const float mu = s * (1.f / DI);
        const float var = sq * (1.f / DI) - mu * mu;
        const float rs = rsqrtf(var + 1e-5f);
#pragma unroll
        for (int i = 0; i < 12; i++) {
            const int k = lane + 32 * i;
            const float zn = g_z[row * DI + k];
            const float sig = 1.f / (1.f + __expf(-zn));
            const float g = fmaf((v[i] - mu) * rs, lng[k], lnb[k]);
            g_xi[row * DI + k] = g * zn * sig;
        }
    }
}

// ---------------- k_gemm_out: out = yg @ Wout, 64-row tiles (768 blocks) ----------------
// smem floats: A 2 stages @ 0 / 2304; Bh @ 4608 + st*2304; Bl @ 9216 + st*2304. 13824 fl.
__global__ __launch_bounds__(256) void k_gemm_out(float* __restrict__ out)
{
    extern __shared__ float sm[];
    const uint32_t sbase = (uint32_t)__cvta_generic_to_shared(sm);
    const int tid = threadIdx.x;
    const int wid = tid >> 5, t = tid & 31;
    const int m0 = blockIdx.x * 64, n0 = blockIdx.y * 64;
    const int wr = wid & 1, wc = wid >> 1;   // 2 row x 4 col groups
    const int g = t >> 2, c = t & 3, c2 = c * 2;

    float acc[2][2][4];
#pragma unroll
    for (int mt = 0; mt < 2; mt++)
#pragma unroll
        for (int nt = 0; nt < 2; nt++)
#pragma unroll
            for (int e = 0; e < 4; e++) acc[mt][nt][e] = 0.f;

    const int lr = tid >> 2;            // 0..63
    const int lh = (tid & 3) * 8;
    const float* arow = g_xi + (size_t)(m0 + lr) * DI + lh;
    const float* bhrow = g_wohi + (size_t)(n0 + lr) * DI + lh;
    const float* blrow = g_wolo + (size_t)(n0 + lr) * DI + lh;
    const uint32_t adst = sbase + (uint32_t)(lr * AP + lh) * 4;
    const uint32_t bhdst = sbase + (uint32_t)(4608 + lr * AP + lh) * 4;
    const uint32_t bldst = sbase + (uint32_t)(9216 + lr * AP + lh) * 4;

#define GO_ISSUE(i) do { \
        const int st_ = (i) & 1; const int kc_ = (i) * 32; \
        CP16(adst + (uint32_t)(st_ * HSTG) * 4, arow + kc_); \
        CP16(adst + (uint32_t)(st_ * HSTG + 4) * 4, arow + kc_ + 4); \
        CP16(bhdst + (uint32_t)(st_ * HSTG) * 4, bhrow + kc_); \
        CP16(bhdst + (uint32_t)(st_ * HSTG + 4) * 4, bhrow + kc_ + 4); \
        CP16(bldst + (uint32_t)(st_ * HSTG) * 4, blrow + kc_); \
        CP16(bldst + (uint32_t)(st_ * HSTG + 4) * 4, blrow + kc_ + 4); \
        CP_COMMIT(); \
    } while (0)

    GO_ISSUE(0);

    for (int i = 0; i < 12; i++) {
        if (i + 1 < 12) { GO_ISSUE(i + 1); CP_WAIT1(); }
        else CP_WAIT0();
        __syncthreads();

        const float* cA = sm + (i & 1) * HSTG;
        const float* cBh = sm + 4608 + (i & 1) * HSTG;
        const float* cBl = sm + 9216 + (i & 1) * HSTG;
#pragma unroll
        for (int ks = 0; ks < 4; ks++) {
            const int K0 = ks * 8;
            uint32_t ah[2][4], al[2][4];
#pragma unroll
            for (int mt = 0; mt < 2; mt++) {
                const int R = wr * 32 + mt * 16;
#pragma unroll
                for (int j = 0; j < 4; j++) {
                    const int rr = R + g + (j & 1) * 8;
                    const int ccol = K0 + c + (j >> 1) * 4;
                    const float raw = cA[rr * AP + ccol];
                    const float hv = tf32v(raw);
                    ah[mt][j] = __float_as_uint(hv);
                    al[mt][j] = f2tf32(raw - hv);
                }
            }
#pragma unroll
            for (int nt = 0; nt < 2; nt++) {
                const int N = wc * 16 + nt * 8;
                uint32_t bh[2], bl[2];
                bh[0] = *(const uint32_t*)&cBh[(N + g) * AP + K0 + c];
                bh[1] = *(const uint32_t*)&cBh[(N + g) * AP + K0 + c + 4];
                bl[0] = *(const uint32_t*)&cBl[(N + g) * AP + K0 + c];
                bl[1] = *(const uint32_t*)&cBl[(N + g) * AP + K0 + c + 4];
#pragma unroll
                for (int mt = 0; mt < 2; mt++) {
                    mma_tf32(acc[mt][nt], ah[mt], bh);
                    mma_tf32(acc[mt][nt], ah[mt], bl);
                    mma_tf32(acc[mt][nt], al[mt], bh);
                }
            }
        }
        __syncthreads();
    }
#undef GO_ISSUE

#pragma unroll
    for (int mt = 0; mt < 2; mt++) {
#pragma unroll
        for (int nt = 0; nt < 2; nt++) {
            const int col = n0 + wc * 16 + nt * 8 + c2;
            const int r0 = m0 + wr * 32 + mt * 16 + g;
            *(float2*)&out[(size_t)r0 * CM + col] =
                make_float2(acc[mt][nt][0], acc[mt][nt][1]);
            *(float2*)&out[(size_t)(r0 + 8) * CM + col] =
                make_float2(acc[mt][nt][2], acc[mt][nt][3]);
        }
    }
}

// ---------------- launch ----------------
extern "C" void kernel_launch(void* const* d_in, const int* in_sizes, int n_in,
                              void* d_out, int out_size)
{
    const float* x      = (const float*)d_in[0];
    const float* prompt = (const float*)d_in[1];
    const float* W_in   = (const float*)d_in[2];
    const float* conv_w = (const float*)d_in[3];
    const float* conv_b = (const float*)d_in[4];
    const float* Wx     = (const float*)d_in[5];
    const float* Wdt    = (const float*)d_in[6];
    const float* b_dt   = (const float*)d_in[7];
    const float* A_log  = (const float*)d_in[8];
    const float* Dv     = (const float*)d_in[9];
    const float* Wp     = (const float*)d_in[10];
    const float* ln_g   = (const float*)d_in[11];
    const float* ln_b   = (const float*)d_in[12];
    const float* Wout   = (const float*)d_in[13];
    float* out = (float*)d_out;

    static bool attr_set = false;
    if (!attr_set) {
        cudaFuncSetAttribute(k_conv, cudaFuncAttributeMaxDynamicSharedMemorySize, 51200);
        cudaFuncSetAttribute(k_gemm_tf32, cudaFuncAttributeMaxDynamicSharedMemorySize, 53248);
        cudaFuncSetAttribute(k_proj_mma, cudaFuncAttributeMaxDynamicSharedMemorySize, 46080);
        cudaFuncSetAttribute(k_gemm_out, cudaFuncAttributeMaxDynamicSharedMemorySize, 55296);
        attr_set = true;
    }

    k_prep_all<<<(PREP_W + PREP_PW + PREP_WO + 255) / 256, 256>>>(W_in, Wx, Wp, Wout);
    k_gemm_tf32<<<dim3(M_ROWS / 128, NX / 64), 256, 53248>>>(x);
    k_conv<<<dim3(64, 3, BATCH), dim3(128, 8), 51200>>>(conv_w, conv_b);
    k_proj_mma<<<M_ROWS / 32, 256, 46080>>>(prompt);
    k_delta<<<M_ROWS / 8, DI>>>(Wdt, b_dt);
    k_scan1<<<dim3(DI / 128, NCH, BATCH), 128>>>(A_log);
    k_scan2<<<(BDN + 255) / 256, 256>>>();
    k_scan3<<<dim3(DI / 128, NCH, BATCH), 128>>>(A_log, Dv);
    k_lngate<<<M_ROWS / 16, 256>>>(ln_g, ln_b);
    k_gemm_out<<<dim3(M_ROWS / 64, 3), 256, 55296>>>(out);
}

// round 16
// speedup vs baseline: 1.1159x; 1.1159x over previous
#include <cuda_runtime.h>
#include <cuda_bf16.h>
#include <cstdint>

#define BATCH 4
#define L 4096
#define CM 192
#define DI 384
#define DS 16
#define DTR 12
#define M_ROWS (BATCH * L)   // 16384
#define NCH 64
#define CHL (L / NCH)        // 64
#define BDN (BATCH * DI * DS) // 24576
#define NX (2 * DI)          // 768
#define KC 576
#define NP 64
#define AP 36
#define ASTG (128 * AP)
#define HSTG (64 * AP)
#define BSTG (64 * AP)
#define BFRG 2048

// ---------------- scratch ----------------
__device__ float g_xi[(size_t)M_ROWS * DI];
__device__ float g_z[(size_t)M_ROWS * DI];
__device__ float g_u[(size_t)M_ROWS * DI];
__device__ float g_delta[(size_t)M_ROWS * DI];
__device__ float g_dtr[(size_t)M_ROWS * DTR];
__device__ float g_Bs[(size_t)M_ROWS * DS];
__device__ float g_Cs[(size_t)M_ROWS * DS];
__device__ float g_y[(size_t)M_ROWS * DI];
__device__ float g_hpart[(size_t)NCH * BDN];
__device__ float g_aP[(size_t)NCH * BDN];
__device__ float g_hin[(size_t)NCH * BDN];
__device__ float g_wtf[(size_t)NX * CM];
__device__ float g_pwhi[(size_t)NP * KC];
__device__ float g_pwlo[(size_t)NP * KC];
__device__ float g_wohi[(size_t)CM * DI];
__device__ float g_wolo[(size_t)CM * DI];

__device__ __forceinline__ uint32_t f2tf32(float f)
{
    uint32_t r;
    asm("cvt.rna.tf32.f32 %0, %1;" : "=r"(r) : "f"(f));
    return r;
}
__device__ __forceinline__ float tf32v(float f) { return __uint_as_float(f2tf32(f)); }

#define CP16(dst, src) \
    asm volatile("cp.async.cg.shared.global [%0], [%1], 16;" :: "r"(dst), "l"(src))
#define CP_COMMIT() asm volatile("cp.async.commit_group;" ::: "memory")
#define CP_WAIT0()  asm volatile("cp.async.wait_group 0;" ::: "memory")
#define CP_WAIT1()  asm volatile("cp.async.wait_group 1;" ::: "memory")

// ---------------- merged prep kernel ----------------
#define PREP_W  (CM * NX)
#define PREP_PW (NP * KC)
#define PREP_WO (CM * DI)
__global__ void k_prep_all(const float* __restrict__ Win, const float* __restrict__ Wx,
                           const float* __restrict__ Wp, const float* __restrict__ Wout)
{
    const int i = blockIdx.x * 256 + threadIdx.x;
    if (i < PREP_W) {
        const int k = i / NX, n = i % NX;
        const int ncb = n >> 6, j = (n & 63) >> 3, gg = n & 7;
        const int kci = k >> 5, ks = (k >> 3) & 3, cc = k & 7;
        const int slot = cc >> 2, tl = gg * 4 + (cc & 3);
        const size_t off = (size_t)ncb * 12288 + kci * 2048 + j * 256 + ks * 64 + tl * 2 + slot;
        g_wtf[off] = tf32v(Win[i]);
    } else if (i < PREP_W + PREP_PW) {
        const int e = i - PREP_W;
        const int n = e / KC, k = e % KC;
        float v = 0.f;
        if (n < 44) {
            if (k < DI) v = Wx[(size_t)k * 44 + n];
            else if (n >= 28) v = Wp[(size_t)(k - DI) * DS + (n - 28)];
        }
        const float hi = tf32v(v);
        g_pwhi[e] = hi;
        g_pwlo[e] = tf32v(v - hi);
    } else if (i < PREP_W + PREP_PW + PREP_WO) {
        const int e = i - PREP_W - PREP_PW;
        const int k = e / CM, n = e % CM;
        const float v = Wout[e];
        const float hi = tf32v(v);
        g_wohi[(size_t)n * DI + k] = hi;
        g_wolo[(size_t)n * DI + k] = tf32v(v - hi);
    }
}

__device__ __forceinline__ void mma_tf32(float* d, const uint32_t* a, const uint32_t* b)
{
    asm volatile(
        "mma.sync.aligned.m16n8k8.row.col.f32.tf32.tf32.f32 "
        "{%0,%1,%2,%3}, {%4,%5,%6,%7}, {%8,%9}, {%0,%1,%2,%3};"
        : "+f"(d[0]), "+f"(d[1]), "+f"(d[2]), "+f"(d[3])
        : "r"(a[0]), "r"(a[1]), "r"(a[2]), "r"(a[3]), "r"(b[0]), "r"(b[1]));
}

// ---------------- K1: xz = x @ W_in (tf32, 128x64 tile, frag-packed B) ----------------
__global__ __launch_bounds__(256) void k_gemm_tf32(const float* __restrict__ X)
{
    extern __shared__ float sm[];
    const uint32_t sbase = (uint32_t)__cvta_generic_to_shared(sm);
    const int tid = threadIdx.x;
    const int wid = tid >> 5, t = tid & 31;
    const int m0 = blockIdx.x * 128, ncb = blockIdx.y;
    const int wr = wid & 3, wc = wid >> 2;
    const int g = t >> 2, c = t & 3, c2 = c * 2;

    float acc[2][4][4];
#pragma unroll
    for (int mt = 0; mt < 2; mt++)
#pragma unroll
        for (int nt = 0; nt < 4; nt++)
#pragma unroll
            for (int e = 0; e < 4; e++) acc[mt][nt][e] = 0.f;

    const int lr = tid >> 1;
    const int lh = (tid & 1) * 16;
    const float* arow = X + (size_t)(m0 + lr) * CM + lh;
    const float* bbase = g_wtf + (size_t)ncb * 12288;
    const uint32_t adst = sbase + (uint32_t)(lr * AP + lh) * 4;
    const uint32_t bdst = sbase + (uint32_t)(9216 + tid * 4) * 4;

#define K1_ISSUE(i) do { \
        const int st_ = (i) & 1; const int kc_ = (i) * 32; \
        _Pragma("unroll") \
        for (int q = 0; q < 4; q++) \
            CP16(adst + (uint32_t)(st_ * ASTG + q * 4) * 4, arow + kc_ + q * 4); \
        CP16(bdst + (uint32_t)(st_ * BFRG) * 4, bbase + (i) * 2048 + tid * 4); \
        CP16(bdst + (uint32_t)(st_ * BFRG + 1024) * 4, bbase + (i) * 2048 + 1024 + tid * 4); \
        CP_COMMIT(); \
    } while (0)

    K1_ISSUE(0);

    for (int i = 0; i < 6; i++) {
        if (i + 1 < 6) { K1_ISSUE(i + 1); CP_WAIT1(); }
        else CP_WAIT0();
        __syncthreads();

        const float* cA = sm + (i & 1) * ASTG;
        const float* cB = sm + 9216 + (i & 1) * BFRG;
#pragma unroll
        for (int ks = 0; ks < 4; ks++) {
            const int K0 = ks * 8;
            uint32_t af[2][4];
#pragma unroll
            for (int mt = 0; mt < 2; mt++) {
                const int R = wr * 32 + mt * 16;
                af[mt][0] = f2tf32(cA[(R + g) * AP + K0 + c]);
                af[mt][1] = f2tf32(cA[(R + g + 8) * AP + K0 + c]);
                af[mt][2] = f2tf32(cA[(R + g) * AP + K0 + c + 4]);
                af[mt][3] = f2tf32(cA[(R + g + 8) * AP + K0 + c + 4]);
            }
#pragma unroll
            for (int nt = 0; nt < 4; nt++) {
                const int j = wc * 4 + nt;
                const float2 bv = *(const float2*)&cB[(j * 4 + ks) * 64 + t * 2];
                uint32_t bf[2] = {__float_as_uint(bv.x), __float_as_uint(bv.y)};
#pragma unroll
                for (int mt = 0; mt < 2; mt++)
                    mma_tf32(acc[mt][nt], af[mt], bf);
            }
        }
        __syncthreads();
    }
#undef K1_ISSUE

    const int n0 = ncb * 64;
    const bool toZ = (n0 >= DI);
#pragma unroll
    for (int mt = 0; mt < 2; mt++) {
#pragma unroll
        for (int nt = 0; nt < 4; nt++) {
            int nc = n0 + wc * 32 + nt * 8 + c2;
            if (toZ) nc -= DI;
            const int r0 = m0 + wr * 32 + mt * 16 + g;
            float* base = toZ ? g_z : g_xi;
            *(float2*)&base[(size_t)r0 * DI + nc] =
                make_float2(acc[mt][nt][0], acc[mt][nt][1]);
            *(float2*)&base[(size_t)(r0 + 8) * DI + nc] =
                make_float2(acc[mt][nt][2], acc[mt][nt][3]);
        }
    }
}

// ---------------- conv (R12 version) ----------------
__global__ __launch_bounds__(1024) void k_conv(const float* __restrict__ cw,
                                               const float* __restrict__ cb)
{
    extern __shared__ float cs[];
    const int b = blockIdx.z;
    const int d = blockIdx.y * 128 + threadIdx.x;
    const int h0 = (blockIdx.x >> 3) * 8;
    const int w0 = (blockIdx.x & 7) * 8;
    const int tx = threadIdx.x, ty = threadIdx.y;
    const size_t base = (size_t)b * L * DI;

#pragma unroll
    for (int i = 0; i < 13; i++) {
        const int p = ty + 8 * i;
        if (p < 100) {
            const int rr = p / 10, cc = p % 10;
            const int hh = h0 + rr - 1, ww = w0 + cc - 1;
            float v = 0.f;
            if (hh >= 0 && hh < 64 && ww >= 0 && ww < 64)
                v = g_xi[base + (size_t)(hh * 64 + ww) * DI + d];
            cs[p * 128 + tx] = v;
        }
    }
    __syncthreads();

    float W[9];
#pragma unroll
    for (int i = 0; i < 9; i++) W[i] = cw[d * 9 + i];
    const float bias = cb[d];

    float acc[8];
#pragma unroll
    for (int j = 0; j < 8; j++) acc[j] = bias;

#pragma unroll
    for (int r = 0; r < 3; r++) {
        float rv[10];
#pragma unroll
        for (int cc = 0; cc < 10; cc++) rv[cc] = cs[((ty + r) * 10 + cc) * 128 + tx];
#pragma unroll
        for (int j = 0; j < 8; j++) {
            acc[j] = fmaf(rv[j],     W[r * 3 + 0], acc[j]);
            acc[j] = fmaf(rv[j + 1], W[r * 3 + 1], acc[j]);
            acc[j] = fmaf(rv[j + 2], W[r * 3 + 2], acc[j]);
        }
    }
#pragma unroll
    for (int j = 0; j < 8; j++) {
        const float sig = 1.f / (1.f + __expf(-acc[j]));
        g_u[base + (size_t)((h0 + ty) * 64 + w0 + j) * DI + d] = acc[j] * sig;
    }
}

// ---------------- k_proj_mma: [u|prompt] @ Wcat, 64-row tiles (R14 version) ----------------
__global__ __launch_bounds__(256) void k_proj_mma(const float* __restrict__ prompt)
{
    extern __shared__ float sm[];
    const uint32_t sbase = (uint32_t)__cvta_generic_to_shared(sm);
    const int tid = threadIdx.x;
    const int wid = tid >> 5, t = tid & 31;
    const int m0 = blockIdx.x * 64;
    const int wr = wid & 1, wc = wid >> 1;
    const int g = t >> 2, c = t & 3, c2 = c * 2;

    float acc[2][2][4];
#pragma unroll
    for (int mt = 0; mt < 2; mt++)
#pragma unroll
        for (int nt = 0; nt < 2; nt++)
#pragma unroll
            for (int e = 0; e < 4; e++) acc[mt][nt][e] = 0.f;

    const int lr = tid >> 2;
    const int lh = (tid & 3) * 8;
    const float* urow = g_u + (size_t)(m0 + lr) * DI + lh;
    const float* prow = prompt + (size_t)(m0 + lr) * CM + lh;
    const float* bhrow = g_pwhi + (size_t)lr * KC + lh;
    const float* blrow = g_pwlo + (size_t)lr * KC + lh;
    const uint32_t adst = sbase + (uint32_t)(lr * AP + lh) * 4;
    const uint32_t bhdst = sbase + (uint32_t)(4608 + lr * AP + lh) * 4;
    const uint32_t bldst = sbase + (uint32_t)(9216 + lr * AP + lh) * 4;

#define PJ_ISSUE(i) do { \
        const int st_ = (i) & 1; const int kc_ = (i) * 32; \
        const float* ar_ = (kc_ < DI) ? urow + kc_ : prow + (kc_ - DI); \
        CP16(adst + (uint32_t)(st_ * HSTG) * 4, ar_); \
        CP16(adst + (uint32_t)(st_ * HSTG + 4) * 4, ar_ + 4); \
        CP16(bhdst + (uint32_t)(st_ * HSTG) * 4, bhrow + kc_); \
        CP16(bhdst + (uint32_t)(st_ * HSTG + 4) * 4, bhrow + kc_ + 4); \
        CP16(bldst + (uint32_t)(st_ * HSTG) * 4, blrow + kc_); \
        CP16(bldst + (uint32_t)(st_ * HSTG + 4) * 4, blrow + kc_ + 4); \
        CP_COMMIT(); \
    } while (0)

    PJ_ISSUE(0);

    for (int i = 0; i < 18; i++) {
        if (i + 1 < 18) { PJ_ISSUE(i + 1); CP_WAIT1(); }
        else CP_WAIT0();
        __syncthreads();

        const float* cA = sm + (i & 1) * HSTG;
        const float* cBh = sm + 4608 + (i & 1) * HSTG;
        const float* cBl = sm + 9216 + (i & 1) * HSTG;
#pragma unroll
        for (int ks = 0; ks < 4; ks++) {
            const int K0 = ks * 8;
            uint32_t ah[2][4], al[2][4];
#pragma unroll
            for (int mt = 0; mt < 2; mt++) {
                const int R = wr * 32 + mt * 16;
#pragma unroll
                for (int j = 0; j < 4; j++) {
                    const int rr = R + g + (j & 1) * 8;
                    const int ccol = K0 + c + (j >> 1) * 4;
                    const float raw = cA[rr * AP + ccol];
                    const float hv = tf32v(raw);
                    ah[mt][j] = __float_as_uint(hv);
                    al[mt][j] = f2tf32(raw - hv);
                }
            }
#pragma unroll
            for (int nt = 0; nt < 2; nt++) {
                const int N = wc * 16 + nt * 8;
                uint32_t bh[2], bl[2];
                bh[0] = *(const uint32_t*)&cBh[(N + g) * AP + K0 + c];
                bh[1] = *(const uint32_t*)&cBh[(N + g) * AP + K0 + c + 4];
                bl[0] = *(const uint32_t*)&cBl[(N + g) * AP + K0 + c];
                bl[1] = *(const uint32_t*)&cBl[(N + g) * AP + K0 + c + 4];
#pragma unroll
                for (int mt = 0; mt < 2; mt++) {
                    mma_tf32(acc[mt][nt], ah[mt], bh);
                    mma_tf32(acc[mt][nt], ah[mt], bl);
                    mma_tf32(acc[mt][nt], al[mt], bh);
                }
            }
        }
        __syncthreads();
    }
#undef PJ_ISSUE

#pragma unroll
    for (int mt = 0; mt < 2; mt++) {
#pragma unroll
        for (int nt = 0; nt < 2; nt++) {
            const int col = wc * 16 + nt * 8 + c2;
            const int r0 = m0 + wr * 32 + mt * 16 + g;
#pragma unroll
            for (int hrow = 0; hrow < 2; hrow++) {
                const size_t row = (size_t)(r0 + hrow * 8);
                const float v0 = acc[mt][nt][hrow * 2 + 0];
                const float v1 = acc[mt][nt][hrow * 2 + 1];
                if (col < DTR)
                    *(float2*)&g_dtr[row * DTR + col] = make_float2(v0, v1);
                else if (col < DTR + DS)
                    *(float2*)&g_Bs[row * DS + (col - DTR)] = make_float2(v0, v1);
                else if (col < 44)
                    *(float2*)&g_Cs[row * DS + (col - DTR - DS)] = make_float2(v0, v1);
            }
        }
    }
}

// ---------------- k_delta ----------------
__global__ void k_delta(const float* __restrict__ Wdt, const float* __restrict__ bdt)
{
    __shared__ float sd[8][DTR];
    const int tid = threadIdx.x;
    const int row0 = blockIdx.x * 8;
    if (tid < 8 * DTR) sd[tid / DTR][tid % DTR] = g_dtr[(size_t)(row0 + tid / DTR) * DTR + tid % DTR];
    __syncthreads();

    float w[DTR];
#pragma unroll
    for (int rr = 0; rr < DTR; rr++) w[rr] = Wdt[(size_t)rr * DI + tid];
    const float bb = bdt[tid];
#pragma unroll
    for (int rr = 0; rr < 8; rr++) {
        float acc = bb;
#pragma unroll
        for (int r2 = 0; r2 < DTR; r2++) acc = fmaf(sd[rr][r2], w[r2], acc);
        const float sp = acc > 20.f ? acc : log1pf(__expf(acc));
        g_delta[(size_t)(row0 + rr) * DI + tid] = sp;
    }
}

// ---------------- scan helpers ----------------
__device__ __forceinline__ void pow_chain(float e1, float* av)
{
    const float e2 = e1 * e1, e4 = e2 * e2, e8 = e4 * e4;
    av[0] = e1;       av[1] = e2;       av[2] = e2 * e1;   av[3] = e4;
    av[4] = e4 * e1;  av[5] = e4 * e2;  av[6] = e4 * av[2]; av[7] = e8;
    av[8] = e8 * e1;  av[9] = e8 * e2;  av[10] = e8 * av[2]; av[11] = e8 * e4;
    av[12] = e8 * av[4]; av[13] = e8 * av[5]; av[14] = e8 * av[6]; av[15] = e8 * e8;
}

__device__ __forceinline__ bool a_structured(const float* __restrict__ Alog, int d, float& A0)
{
    A0 = -__expf(Alog[(size_t)d * DS]);
    bool ok = true;
#pragma unroll
    for (int n = 1; n < DS; n++) {
        const float Av = -__expf(Alog[(size_t)d * DS + n]);
        ok &= fabsf(Av - (n + 1) * A0) <= 1e-4f * fabsf((n + 1) * A0);
    }
    return ok;
}

// ---------------- S1 (CHL=64) ----------------
__global__ void k_scan1(const float* __restrict__ Alog)
{
    __shared__ float sB[CHL][DS];
    const int d = blockIdx.x * 128 + threadIdx.x;
    const int c = blockIdx.y;
    const int b = blockIdx.z;
    const int l0 = c * CHL;

    {
        const float4* src = (const float4*)g_Bs + ((size_t)b * L + l0) * 4;
#pragma unroll
        for (int q = 0; q < CHL * DS / 4 / 128; q++)
            ((float4*)sB)[threadIdx.x + q * 128] = src[threadIdx.x + q * 128];
    }

    float A0;
    const bool st = a_structured(Alog, d, A0);
    __syncthreads();

    float h[DS];
#pragma unroll
    for (int n = 0; n < DS; n++) h[n] = 0.f;
    float dsum = 0.f;

    const float* dp = g_delta + ((size_t)b * L + l0) * DI + d;
    const float* up = g_u + ((size_t)b * L + l0) * DI + d;

    if (st) {
        for (int l = 0; l < CHL; l++) {
            const float dl = dp[(size_t)l * DI];
            const float du = dl * up[(size_t)l * DI];
            dsum += dl;
            float av[DS];
            pow_chain(__expf(dl * A0), av);
#pragma unroll
            for (int n = 0; n < DS; n++) h[n] = fmaf(av[n], h[n], du * sB[l][n]);
        }
        float av[DS];
        pow_chain(__expf(dsum * A0), av);
        const size_t base = (size_t)c * BDN + ((size_t)b * DI + d) * DS;
#pragma unroll
        for (int n = 0; n < DS; n++) {
            g_hpart[base + n] = h[n];
            g_aP[base + n] = av[n];
        }
    } else {
        float A[DS];
#pragma unroll
        for (int n = 0; n < DS; n++) A[n] = -__expf(Alog[(size_t)d * DS + n]);
        for (int l = 0; l < CHL; l++) {
            const float dl = dp[(size_t)l * DI];
            const float du = dl * up[(size_t)l * DI];
            dsum += dl;
#pragma unroll
            for (int n = 0; n < DS; n++)
                h[n] = fmaf(__expf(dl * A[n]), h[n], du * sB[l][n]);
        }
        const size_t base = (size_t)c * BDN + ((size_t)b * DI + d) * DS;
#pragma unroll
        for (int n = 0; n < DS; n++) {
            g_hpart[base + n] = h[n];
            g_aP[base + n] = __expf(A[n] * dsum);
        }
    }
}

// ---------------- S2 (NCH=64) ----------------
__global__ void k_scan2()
{
    const int idx = blockIdx.x * 256 + threadIdx.x;
    if (idx >= BDN) return;
    float h = 0.f;
    for (int c = 0; c < NCH; c++) {
        const size_t o = (size_t)c * BDN + idx;
        g_hin[o] = h;
        h = fmaf(g_aP[o], h, g_hpart[o]);
    }
}

// ---------------- S3 (CHL=64) ----------------
__global__ void k_scan3(const float* __restrict__ Alog, const float* __restrict__ Dvec)
{
    __shared__ float sB[CHL][DS];
    __shared__ float sC[CHL][DS];
    const int d = blockIdx.x * 128 + threadIdx.x;
    const int c = blockIdx.y;
    const int b = blockIdx.z;
    const int l0 = c * CHL;

    {
        const float4* srcB = (const float4*)g_Bs + ((size_t)b * L + l0) * 4;
        const float4* srcC = (const float4*)g_Cs + ((size_t)b * L + l0) * 4;
#pragma unroll
        for (int q = 0; q < CHL * DS / 4 / 128; q++) {
            ((float4*)sB)[threadIdx.x + q * 128] = srcB[threadIdx.x + q * 128];
            ((float4*)sC)[threadIdx.x + q * 128] = srcC[threadIdx.x + q * 128];
        }
    }

    float A0;
    const bool st = a_structured(Alog, d, A0);
    const float Dd = Dvec[d];
    __syncthreads();

    float h[DS];
    {
        const size_t base = (size_t)c * BDN + ((size_t)b * DI + d) * DS;
#pragma unroll
        for (int n = 0; n < DS; n++) h[n] = g_hin[base + n];
    }

    const float* dp = g_delta + ((size_t)b * L + l0) * DI + d;
    const float* up = g_u + ((size_t)b * L + l0) * DI + d;
    float* yp = g_y + ((size_t)b * L + l0) * DI + d;

    if (st) {
        for (int l = 0; l < CHL; l++) {
            const float dl = dp[(size_t)l * DI];
            const float uu = up[(size_t)l * DI];
            const float du = dl * uu;
            float av[DS];
            pow_chain(__expf(dl * A0), av);
            float y = uu * Dd;
#pragma unroll
            for (int n = 0; n < DS; n++) {
                h[n] = fmaf(av[n], h[n], du * sB[l][n]);
                y = fmaf(h[n], sC[l][n], y);
            }
            yp[(size_t)l * DI] = y;
        }
    } else {
        float A[DS];
#pragma unroll
        for (int n = 0; n < DS; n++) A[n] = -__expf(Alog[(size_t)d * DS + n]);
        for (int l = 0; l < CHL; l++) {
            const float dl = dp[(size_t)l * DI];
            const float uu = up[(size_t)l * DI];
            const float du = dl * uu;
            float y = uu * Dd;
#pragma unroll
            for (int n = 0; n < DS; n++) {
                h[n] = fmaf(__expf(dl * A[n]), h[n], du * sB[l][n]);
                y = fmaf(h[n], sC[l][n], y);
            }
            yp[(size_t)l * DI] = y;
        }
    }
}

// ---------------- k_lngate ----------------
__global__ __launch_bounds__(256) void k_lngate(const float* __restrict__ lng,
                                                const float* __restrict__ lnb)
{
    const int tid = threadIdx.x;
    const int r0 = blockIdx.x * 16;
    const int warp = tid >> 5, lane = tid & 31;

#pragma unroll
    for (int rr = 0; rr < 2; rr++) {
        const int r = warp * 2 + rr;
        const size_t row = (size_t)(r0 + r);
        float v[12];
        float s = 0.f, sq = 0.f;
#pragma unroll
        for (int i = 0; i < 12; i++) {
            v[i] = g_y[row * DI + lane + 32 * i];
            s += v[i];
            sq = fmaf(v[i], v[i], sq);
        }
#pragma unroll
        for (int o = 16; o > 0; o >>= 1) {
            s += __shfl_xor_sync(0xFFFFFFFFu, s, o);
            sq += __shfl_xor_sync(0xFFFFFFFFu, sq, o);
        }
        const float mu = s * (1.f / DI);
        const float var = sq * (1.f / DI) - mu * mu;
        const float rs = rsqrtf(var + 1e-5f);
#pragma unroll
        for (int i = 0; i < 12; i++) {
            const int k = lane + 32 * i;
            const float zn = g_z[row * DI + k];
            const float sig = 1.f / (1.f + __expf(-zn));
            const float g = fmaf((v[i] - mu) * rs, lng[k], lnb[k]);
            g_xi[row * DI + k] = g * zn * sig;
        }
    }
}

// ---------------- k_gemm_out (R12 version, 128-row tiles) ----------------
__global__ __launch_bounds__(256) void k_gemm_out(float* __restrict__ out)
{
    extern __shared__ float sm[];
    const uint32_t sbase = (uint32_t)__cvta_generic_to_shared(sm);
    const int tid = threadIdx.x;
    const int wid = tid >> 5, t = tid & 31;
    const int m0 = blockIdx.x * 128, n0 = blockIdx.y * 64;
    const int wr = wid & 3, wc = wid >> 2;
    const int g = t >> 2, c = t & 3, c2 = c * 2;

    float acc[2][4][4];
#pragma unroll
    for (int mt = 0; mt < 2; mt++)
#pragma unroll
        for (int nt = 0; nt < 4; nt++)
#pragma unroll
            for (int e = 0; e < 4; e++) acc[mt][nt][e] = 0.f;

    const int lr = tid >> 1;
    const int lh = (tid & 1) * 16;
    const int lrB = tid >> 2;
    const int lhB = (tid & 3) * 8;
    const float* arow = g_xi + (size_t)(m0 + lr) * DI + lh;
    const float* bhrow = g_wohi + (size_t)(n0 + lrB) * DI + lhB;
    const float* blrow = g_wolo + (size_t)(n0 + lrB) * DI + lhB;
    const uint32_t adst = sbase + (uint32_t)(lr * AP + lh) * 4;
    const uint32_t bhdst = sbase + (uint32_t)(9216 + lrB * AP + lhB) * 4;
    const uint32_t bldst = sbase + (uint32_t)(13824 + lrB * AP + lhB) * 4;

#define GO_ISSUE(i) do { \
        const int st_ = (i) & 1; const int kc_ = (i) * 32; \
        _Pragma("unroll") \
        for (int q = 0; q < 4; q++) \
            CP16(adst + (uint32_t)(st_ * ASTG + q * 4) * 4, arow + kc_ + q * 4); \
        _Pragma("unroll") \
        for (int q = 0; q < 2; q++) { \
            CP16(bhdst + (uint32_t)(st_ * BSTG + q * 4) * 4, bhrow + kc_ + q * 4); \
            CP16(bldst + (uint32_t)(st_ * BSTG + q * 4) * 4, blrow + kc_ + q * 4); \
        } \
        CP_COMMIT(); \
    } while (0)

    GO_ISSUE(0);

    for (int i = 0; i < 12; i++) {
        if (i + 1 < 12) { GO_ISSUE(i + 1); CP_WAIT1(); }
        else CP_WAIT0();
        __syncthreads();

        const float* cA = sm + (i & 1) * ASTG;
        const float* cBh = sm + 9216 + (i & 1) * BSTG;
        const float* cBl = sm + 13824 + (i & 1) * BSTG;
#pragma unroll
        for (int ks = 0; ks < 4; ks++) {
            const int K0 = ks * 8;
            uint32_t ah[2][4], al[2][4];
#pragma unroll
            for (int mt = 0; mt < 2; mt++) {
                const int R = wr * 32 + mt * 16;
#pragma unroll
                for (int j = 0; j < 4; j++) {
                    const int rr = R + g + (j & 1) * 8;
                    const int ccol = K0 + c + (j >> 1) * 4;
                    const float raw = cA[rr * AP + ccol];
                    const float hv = tf32v(raw);
                    ah[mt][j] = __float_as_uint(hv);
                    al[mt][j] = f2tf32(raw - hv);
                }
            }
#pragma unroll
            for (int nt = 0; nt < 4; nt++) {
                const int N = wc * 32 + nt * 8;
                uint32_t bh[2], bl[2];
                bh[0] = *(const uint32_t*)&cBh[(N + g) * AP + K0 + c];
                bh[1] = *(const uint32_t*)&cBh[(N + g) * AP + K0 + c + 4];
                bl[0] = *(const uint32_t*)&cBl[(N + g) * AP + K0 + c];
                bl[1] = *(const uint32_t*)&cBl[(N + g) * AP + K0 + c + 4];
#pragma unroll
                for (int mt = 0; mt < 2; mt++) {
                    mma_tf32(acc[mt][nt], ah[mt], bh);
                    mma_tf32(acc[mt][nt], ah[mt], bl);
                    mma_tf32(acc[mt][nt], al[mt], bh);
                }
            }
        }
        __syncthreads();
    }
#undef GO_ISSUE

#pragma unroll
    for (int mt = 0; mt < 2; mt++) {
#pragma unroll
        for (int nt = 0; nt < 4; nt++) {
            const int col = n0 + wc * 32 + nt * 8 + c2;
            const int r0 = m0 + wr * 32 + mt * 16 + g;
            *(float2*)&out[(size_t)r0 * CM + col] =
                make_float2(acc[mt][nt][0], acc[mt][nt][1]);
            *(float2*)&out[(size_t)(r0 + 8) * CM + col] =
                make_float2(acc[mt][nt][2], acc[mt][nt][3]);
        }
    }
}

// ---------------- launch ----------------
extern "C" void kernel_launch(void* const* d_in, const int* in_sizes, int n_in,
                              void* d_out, int out_size)
{
    const float* x      = (const float*)d_in[0];
    const float* prompt = (const float*)d_in[1];
    const float* W_in   = (const float*)d_in[2];
    const float* conv_w = (const float*)d_in[3];
    const float* conv_b = (const float*)d_in[4];
    const float* Wx     = (const float*)d_in[5];
    const float* Wdt    = (const float*)d_in[6];
    const float* b_dt   = (const float*)d_in[7];
    const float* A_log  = (const float*)d_in[8];
    const float* Dv     = (const float*)d_in[9];
    const float* Wp     = (const float*)d_in[10];
    const float* ln_g   = (const float*)d_in[11];
    const float* ln_b   = (const float*)d_in[12];
    const float* Wout   = (const float*)d_in[13];
    float* out = (float*)d_out;

    static bool attr_set = false;
    if (!attr_set) {
        cudaFuncSetAttribute(k_conv, cudaFuncAttributeMaxDynamicSharedMemorySize, 51200);
        cudaFuncSetAttribute(k_gemm_tf32, cudaFuncAttributeMaxDynamicSharedMemorySize, 53248);
        cudaFuncSetAttribute(k_proj_mma, cudaFuncAttributeMaxDynamicSharedMemorySize, 55296);
        cudaFuncSetAttribute(k_gemm_out, cudaFuncAttributeMaxDynamicSharedMemorySize, 73728);
        attr_set = true;
    }

    k_prep_all<<<(PREP_W + PREP_PW + PREP_WO + 255) / 256, 256>>>(W_in, Wx, Wp, Wout);
    k_gemm_tf32<<<dim3(M_ROWS / 128, NX / 64), 256, 53248>>>(x);
    k_conv<<<dim3(64, 3, BATCH), dim3(128, 8), 51200>>>(conv_w, conv_b);
    k_proj_mma<<<M_ROWS / 64, 256, 55296>>>(prompt);
    k_delta<<<M_ROWS / 8, DI>>>(Wdt, b_dt);
    k_scan1<<<dim3(DI / 128, NCH, BATCH), 128>>>(A_log);
    k_scan2<<<(BDN + 255) / 256, 256>>>();
    k_scan3<<<dim3(DI / 128, NCH, BATCH), 128>>>(A_log, Dv);
    k_lngate<<<M_ROWS / 16, 256>>>(ln_g, ln_b);
    k_gemm_out<<<dim3(M_ROWS / 128, 3), 256, 73728>>>(out);
}